// round 3
// baseline (speedup 1.0000x reference)
#include <cuda_runtime.h>
#include <cstdint>

#define N_MACRO 50000
#define D_FEAT  128
#define CHUNK   256   // gather entries per warp

// scratch for per-segment counts (device global: no allocations allowed)
__device__ float g_counts[N_MACRO];

// ---------------------------------------------------------------------------
// Kernel 1: zero output + counts
// ---------------------------------------------------------------------------
__global__ void sp_zero_kernel(float* __restrict__ out) {
    const int total_out = N_MACRO * D_FEAT;
    int stride = gridDim.x * blockDim.x;
    for (int i = blockIdx.x * blockDim.x + threadIdx.x; i < total_out; i += stride)
        out[i] = 0.0f;
    for (int i = blockIdx.x * blockDim.x + threadIdx.x; i < N_MACRO; i += stride)
        g_counts[i] = 0.0f;
}

// ---------------------------------------------------------------------------
// Kernel 2: segmented gather-accumulate.
// Each warp owns CHUNK contiguous gather entries. Segment ids are sorted, so
// a warp accumulates a register-resident run sum (lane owns 4 dims = float4)
// and flushes via atomicAdd only on segment change / chunk end.
// ---------------------------------------------------------------------------
__global__ void sp_scatter_kernel(const float* __restrict__ feat,
                                  const int*   __restrict__ node_ids,
                                  const int*   __restrict__ seg_ids,
                                  float*       __restrict__ out,
                                  int n) {
    const int gwarp = (blockIdx.x * blockDim.x + threadIdx.x) >> 5;
    const int lane  = threadIdx.x & 31;

    int start = gwarp * CHUNK;
    if (start >= n) return;
    int end = min(start + CHUNK, n);

    float4 acc = make_float4(0.f, 0.f, 0.f, 0.f);
    int cnt = 0;
    int cur_seg = __ldg(&seg_ids[start]);

    for (int j = start; j < end; ++j) {
        int s = __ldg(&seg_ids[j]);          // broadcast load (all lanes same addr)
        if (s != cur_seg) {
            // flush the finished run
            float* o = out + (size_t)cur_seg * D_FEAT + lane * 4;
            atomicAdd(o + 0, acc.x);
            atomicAdd(o + 1, acc.y);
            atomicAdd(o + 2, acc.z);
            atomicAdd(o + 3, acc.w);
            if (lane == 0) atomicAdd(&g_counts[cur_seg], (float)cnt);
            acc = make_float4(0.f, 0.f, 0.f, 0.f);
            cnt = 0;
            cur_seg = s;
        }
        int nid = __ldg(&node_ids[j]);
        const float4 v = *reinterpret_cast<const float4*>(
            feat + (size_t)nid * D_FEAT + lane * 4);
        acc.x += v.x; acc.y += v.y; acc.z += v.z; acc.w += v.w;
        ++cnt;
    }
    // final flush
    float* o = out + (size_t)cur_seg * D_FEAT + lane * 4;
    atomicAdd(o + 0, acc.x);
    atomicAdd(o + 1, acc.y);
    atomicAdd(o + 2, acc.z);
    atomicAdd(o + 3, acc.w);
    if (lane == 0) atomicAdd(&g_counts[cur_seg], (float)cnt);
}

// ---------------------------------------------------------------------------
// Kernel 3: divide by max(count, 1)
// ---------------------------------------------------------------------------
__global__ void sp_div_kernel(float* __restrict__ out) {
    const int total = N_MACRO * D_FEAT;
    int stride = gridDim.x * blockDim.x;
    for (int i = blockIdx.x * blockDim.x + threadIdx.x; i < total; i += stride) {
        float c = g_counts[i >> 7];          // D_FEAT = 128 = 2^7
        out[i] *= (1.0f / fmaxf(c, 1.0f));
    }
}

// ---------------------------------------------------------------------------
// Launch
// inputs (metadata order): node_feature f32 [100000*128], batch_node_ids i32
// [n], batch_macro_node_ids i32 [n], num_macro_nodes (scalar)
// ---------------------------------------------------------------------------
extern "C" void kernel_launch(void* const* d_in, const int* in_sizes, int n_in,
                              void* d_out, int out_size) {
    const float* feat     = (const float*)d_in[0];
    const int*   node_ids = (const int*)d_in[1];
    const int*   seg_ids  = (const int*)d_in[2];
    float*       out      = (float*)d_out;
    const int n = in_sizes[1];

    // 1) zero
    sp_zero_kernel<<<256, 256>>>(out);

    // 2) segmented gather-accumulate
    int n_warps  = (n + CHUNK - 1) / CHUNK;
    int n_blocks = (n_warps * 32 + 255) / 256;
    sp_scatter_kernel<<<n_blocks, 256>>>(feat, node_ids, seg_ids, out, n);

    // 3) divide by counts
    sp_div_kernel<<<256, 256>>>(out);
}

// round 4
// speedup vs baseline: 2.3572x; 2.3572x over previous
#include <cuda_runtime.h>
#include <cstdint>

#define N_MACRO       50000
#define D_FEAT        128
#define SEGS_PER_WARP 8      // 50000 % 8 == 0 -> no partial warps over segments
#define UNROLL        8      // gather-load batch size (MLP)

// ---------------------------------------------------------------------------
// Single fused kernel: per-warp segment ownership via binary search on the
// sorted segment ids. No atomics, no zero pass, no divide pass.
//   warp w -> segments [w*8, w*8+8)
//   lanes 0..8 compute lower_bound(seg_ids, base+lane) in parallel
//   each segment accumulated with 8-deep batched LDG.128 (lane owns 4 dims)
// ---------------------------------------------------------------------------
__global__ void __launch_bounds__(256)
sp_pool_kernel(const float* __restrict__ feat,
               const int*   __restrict__ node_ids,
               const int*   __restrict__ seg_ids,
               float*       __restrict__ out,
               int n)
{
    const int warp = (blockIdx.x * blockDim.x + threadIdx.x) >> 5;
    const int lane = threadIdx.x & 31;
    const int seg_base = warp * SEGS_PER_WARP;
    if (seg_base >= N_MACRO) return;

    // --- boundary search: lane l (l<=8) finds first index with seg >= base+l.
    // All 32 lanes run the loop (lanes >8 redundant) to stay converged.
    int target = seg_base + min(lane, SEGS_PER_WARP);
    int lo = 0, hi = n;
    while (lo < hi) {
        int mid = (lo + hi) >> 1;
        if (__ldg(&seg_ids[mid]) < target) lo = mid + 1;
        else                               hi = mid;
    }
    // lo == lower_bound(target); segment g spans [bound[g], bound[g+1])

    #pragma unroll 1
    for (int g = 0; g < SEGS_PER_WARP; ++g) {
        const int s0 = __shfl_sync(0xffffffffu, lo, g);
        const int s1 = __shfl_sync(0xffffffffu, lo, g + 1);

        float4 acc = make_float4(0.f, 0.f, 0.f, 0.f);

        int j = s0;
        // batched main loop: 8 independent LDG.128 in flight
        for (; j + UNROLL <= s1; j += UNROLL) {
            int nid[UNROLL];
            #pragma unroll
            for (int k = 0; k < UNROLL; ++k)
                nid[k] = __ldg(&node_ids[j + k]);
            float4 v[UNROLL];
            #pragma unroll
            for (int k = 0; k < UNROLL; ++k)
                v[k] = *reinterpret_cast<const float4*>(
                    feat + (size_t)nid[k] * D_FEAT + lane * 4);
            #pragma unroll
            for (int k = 0; k < UNROLL; ++k) {
                acc.x += v[k].x; acc.y += v[k].y;
                acc.z += v[k].z; acc.w += v[k].w;
            }
        }
        // tail
        for (; j < s1; ++j) {
            int nid = __ldg(&node_ids[j]);
            float4 v = *reinterpret_cast<const float4*>(
                feat + (size_t)nid * D_FEAT + lane * 4);
            acc.x += v.x; acc.y += v.y; acc.z += v.z; acc.w += v.w;
        }

        // mean (empty segment -> 0, matching sums / max(counts, 1))
        const int cnt = s1 - s0;
        const float inv = (cnt > 0) ? (1.0f / (float)cnt) : 0.0f;
        float4 r = make_float4(acc.x * inv, acc.y * inv,
                               acc.z * inv, acc.w * inv);
        *reinterpret_cast<float4*>(
            out + (size_t)(seg_base + g) * D_FEAT + lane * 4) = r;
    }
}

// ---------------------------------------------------------------------------
// Launch
// inputs (metadata order): node_feature f32 [100000*128], batch_node_ids i32
// [n], batch_macro_node_ids i32 [n] (sorted), num_macro_nodes (scalar)
// ---------------------------------------------------------------------------
extern "C" void kernel_launch(void* const* d_in, const int* in_sizes, int n_in,
                              void* d_out, int out_size) {
    const float* feat     = (const float*)d_in[0];
    const int*   node_ids = (const int*)d_in[1];
    const int*   seg_ids  = (const int*)d_in[2];
    float*       out      = (float*)d_out;
    const int n = in_sizes[1];

    const int n_warps  = (N_MACRO + SEGS_PER_WARP - 1) / SEGS_PER_WARP; // 6250
    const int n_blocks = (n_warps * 32 + 255) / 256;                    // 782
    sp_pool_kernel<<<n_blocks, 256>>>(feat, node_ids, seg_ids, out, n);
}